// round 16
// baseline (speedup 1.0000x reference)
#include <cuda_runtime.h>
#include <cuda_fp16.h>
#include <cstdint>
#include <math.h>
#include <mma.h>

using namespace nvcuda;

// Problem constants
#define BB   2
#define TT   2048
#define DM   1024
#define NH   16
#define NG   4
#define DH   64
#define HPG  (NH / NG)          // 4
#define MTOT (BB * TT)          // 4096
#define KVD  (NG * DH)          // 256
#define NQKV (DM + 2 * KVD)     // 1536

// Scratch (no cudaMalloc allowed)
static __device__ float  g_Q[(size_t)MTOT * DM];      // raw QKV-gemm Q (pre-rope)
static __device__ float  g_K[(size_t)MTOT * KVD];
static __device__ float  g_V[(size_t)MTOT * KVD];
static __device__ __half g_KpH[(size_t)MTOT * KVD];   // rope'd fp16 [b][t][grp][d]
static __device__ __half g_VpH[(size_t)MTOT * KVD];   // fp16 transposed [b][grp][d][t]
static __device__ __half g_Ah[(size_t)MTOT * DM];     // attention out, fp16
static __device__ __half g_Xh  [(size_t)MTOT * DM];
static __device__ __half g_Wqkvh[(size_t)DM * NQKV];
static __device__ float  g_bqkv[NQKV];
static __device__ __half g_Woh [(size_t)DM * DM];

// ---------------------------------------------------------------------------
// helpers
// ---------------------------------------------------------------------------
__device__ __forceinline__ void cp16(void* s, const void* g) {
    unsigned int sa = (unsigned int)__cvta_generic_to_shared(s);
    asm volatile("cp.async.cg.shared.global [%0], [%1], 16;\n" :: "r"(sa), "l"(g));
}
__device__ __forceinline__ void cp_commit() { asm volatile("cp.async.commit_group;\n"); }
template<int N> __device__ __forceinline__ void cp_wait() {
    asm volatile("cp.async.wait_group %0;\n" :: "n"(N));
}

__device__ __forceinline__ unsigned int pack_h2(float a, float b) {
    __half2 h = __floats2half2_rn(a, b);
    return *(unsigned int*)&h;
}
__device__ __forceinline__ uint2 f4_to_h4(float4 v) {
    uint2 r;
    r.x = pack_h2(v.x, v.y);
    r.y = pack_h2(v.z, v.w);
    return r;
}
// exp2 of two fp16 values packed in one register
__device__ __forceinline__ unsigned int ex2_h2(unsigned int s) {
    unsigned int r;
    asm volatile("ex2.approx.f16x2 %0, %1;" : "=r"(r) : "r"(s));
    return r;
}

// mma.m16n8k16 f16: D(f32) += A(f16) * B(f16); A row-major, B col-major
__device__ __forceinline__ void mma_f16(
    float& d0, float& d1, float& d2, float& d3,
    unsigned int a0, unsigned int a1, unsigned int a2, unsigned int a3,
    unsigned int b0, unsigned int b1)
{
    asm volatile(
        "mma.sync.aligned.m16n8k16.row.col.f32.f16.f16.f32 "
        "{%0,%1,%2,%3}, {%4,%5,%6,%7}, {%8,%9}, {%0,%1,%2,%3};"
        : "+f"(d0), "+f"(d1), "+f"(d2), "+f"(d3)
        : "r"(a0), "r"(a1), "r"(a2), "r"(a3), "r"(b0), "r"(b1));
}

// rope pair: (xe, xo) rotated by angle t*freq(i), then scaled
__device__ __forceinline__ float2 rope_pair(float xe, float xo, int t, int i, float sc) {
    float freq = expf(-((2.0f * (float)i) / (float)DH) * 9.210340371976184f);
    float ang = (float)t * freq;
    float s, c;
    sincosf(ang, &s, &c);
    float2 r;
    r.x = (xe * c - xo * s) * sc;
    r.y = (xe * s + xo * c) * sc;
    return r;
}

// ---------------------------------------------------------------------------
// prepass: convert GEMM operands to fp16; pack Wq|Wk|Wv; concat biases (fp32).
// ---------------------------------------------------------------------------
#define N4_X   (MTOT * DM / 4)
#define N4_QO  (DM * DM / 4)
#define N4_KV  (DM * KVD / 4)
#define N4_B   (NQKV / 4)
#define N4_TOT (N4_X + N4_QO + 2 * N4_KV + N4_QO + N4_B)

__global__ void prep_kernel(
    const float* __restrict__ x,  const float* __restrict__ Wq,
    const float* __restrict__ Wk, const float* __restrict__ Wv,
    const float* __restrict__ Wo,
    const float* __restrict__ bq, const float* __restrict__ bk,
    const float* __restrict__ bv,
    __half* __restrict__ Xh, __half* __restrict__ wqkv,
    __half* __restrict__ wo, float* __restrict__ bqkv)
{
    int i = blockIdx.x * blockDim.x + threadIdx.x;
    if (i >= N4_TOT) return;
    int off = i;
    if (off < N4_X) {
        ((uint2*)Xh)[off] = f4_to_h4(((const float4*)x)[off]);
        return;
    }
    off -= N4_X;
    if (off < N4_QO) {
        int r = off >> 8, c = off & 255;
        ((uint2*)wqkv)[r * (NQKV / 4) + c] = f4_to_h4(((const float4*)Wq)[off]);
        return;
    }
    off -= N4_QO;
    if (off < N4_KV) {
        int r = off >> 6, c = off & 63;
        ((uint2*)wqkv)[r * (NQKV / 4) + 256 + c] = f4_to_h4(((const float4*)Wk)[off]);
        return;
    }
    off -= N4_KV;
    if (off < N4_KV) {
        int r = off >> 6, c = off & 63;
        ((uint2*)wqkv)[r * (NQKV / 4) + 320 + c] = f4_to_h4(((const float4*)Wv)[off]);
        return;
    }
    off -= N4_KV;
    if (off < N4_QO) {
        ((uint2*)wo)[off] = f4_to_h4(((const float4*)Wo)[off]);
        return;
    }
    off -= N4_QO;
    float4 v;
    if (off < 256)      v = ((const float4*)bq)[off];
    else if (off < 320) v = ((const float4*)bk)[off - 256];
    else                v = ((const float4*)bv)[off - 320];
    ((float4*)bqkv)[off] = v;
}

// ---------------------------------------------------------------------------
// FP16 GEMM core (unchanged): 128x128 tile, 4 warps, BK=32, 3-stage.
// ---------------------------------------------------------------------------
#define BKH  32
#define LDAH 40
#define LDBH 136
#define GSTH 3
#define GSMEMH ((GSTH * (128 * LDAH + BKH * LDBH)) * 2)
#define LDBF 132

template<typename EPI>
__device__ __forceinline__ void gemm_core_h(
    const __half* __restrict__ Ap, const __half* __restrict__ Bp, int ldbg,
    const float* __restrict__ biasp, EPI epi)
{
    extern __shared__ __half smh[];
    __half* As = smh;
    __half* Bs = smh + GSTH * 128 * LDAH;

    int tid = threadIdx.x;
    int warp = tid >> 5;
    int wm = warp & 1;
    int wn = warp >> 1;

    wmma::fragment<wmma::accumulator, 16, 16, 16, float> acc[4][4];

    float* bstage = (float*)smh;
    for (int i = tid; i < 16 * 128; i += 128) {
        int r = i >> 7, c = i & 127;
        bstage[r * LDBF + c] = biasp[c];
    }
    __syncthreads();
#pragma unroll
    for (int i = 0; i < 4; i++)
#pragma unroll
        for (int j = 0; j < 4; j++)
            wmma::load_matrix_sync(acc[i][j], &bstage[wn * 64 + j * 16], LDBF,
                                   wmma::mem_row_major);
    __syncthreads();

    const int NIT = DM / BKH;

    auto issueG = [&](int it) {
        int s = it % GSTH, k0 = it * BKH;
        __half* as = &As[s * 128 * LDAH];
        __half* bs = &Bs[s * BKH * LDBH];
#pragma unroll
        for (int i = tid; i < 512; i += 128) {
            int r = i >> 2, c = (i & 3) << 3;
            cp16(&as[r * LDAH + c], Ap + (size_t)r * DM + k0 + c);
        }
#pragma unroll
        for (int i = tid; i < 512; i += 128) {
            int r = i >> 4, c = (i & 15) << 3;
            cp16(&bs[r * LDBH + c], Bp + (size_t)(k0 + r) * ldbg + c);
        }
        cp_commit();
    };

    issueG(0); issueG(1); issueG(2);

    for (int it = 0; it < NIT; it++) {
        if (it + 3 <= NIT) cp_wait<2>();
        else if (it + 2 <= NIT) cp_wait<1>();
        else cp_wait<0>();
        __syncthreads();
        int s = it % GSTH;
        const __half* as = &As[s * 128 * LDAH];
        const __half* bs = &Bs[s * BKH * LDBH];
#pragma unroll
        for (int ks = 0; ks < BKH; ks += 16) {
            wmma::fragment<wmma::matrix_a, 16, 16, 16, __half, wmma::row_major> af[4];
            wmma::fragment<wmma::matrix_b, 16, 16, 16, __half, wmma::row_major> bf[4];
#pragma unroll
            for (int i = 0; i < 4; i++)
                wmma::load_matrix_sync(af[i], &as[(wm * 64 + i * 16) * LDAH + ks], LDAH);
#pragma unroll
            for (int j = 0; j < 4; j++)
                wmma::load_matrix_sync(bf[j], &bs[ks * LDBH + wn * 64 + j * 16], LDBH);
#pragma unroll
            for (int i = 0; i < 4; i++)
#pragma unroll
                for (int j = 0; j < 4; j++)
                    wmma::mma_sync(acc[i][j], af[i], bf[j], acc[i][j]);
        }
        __syncthreads();
        if (it + GSTH < NIT) issueG(it + GSTH);
    }

    epi(acc, wm, wn);
}

// fused QKV GEMM: bn 0..7 -> Q, 8..9 -> K, 10..11 -> V (all fp32 out)
__global__ __launch_bounds__(128, 2) void gemm_qkv_kernel(
    const __half* __restrict__ A, const __half* __restrict__ Bw,
    const float* __restrict__ bias,
    float* __restrict__ Qo, float* __restrict__ Ko, float* __restrict__ Vo)
{
    int bn = blockIdx.x, bm = blockIdx.y;
    float* Cb; int ldc;
    if (bn < 8)       { Cb = Qo + bn * 128;          ldc = DM;  }
    else if (bn < 10) { Cb = Ko + (bn - 8) * 128;    ldc = KVD; }
    else              { Cb = Vo + (bn - 10) * 128;   ldc = KVD; }

    gemm_core_h(A + (size_t)bm * 128 * DM, Bw + bn * 128, NQKV, bias + bn * 128,
        [&](wmma::fragment<wmma::accumulator, 16, 16, 16, float> (&acc)[4][4],
            int wm, int wn) {
            float* Cp = Cb + (size_t)(bm * 128 + wm * 64) * ldc + wn * 64;
#pragma unroll
            for (int i = 0; i < 4; i++)
#pragma unroll
                for (int j = 0; j < 4; j++)
                    wmma::store_matrix_sync(Cp + (size_t)(i * 16) * ldc + j * 16,
                                            acc[i][j], ldc, wmma::mem_row_major);
        });
}

// output projection: out(f32) = Ah(f16) @ Woh(f16) + bo
__global__ __launch_bounds__(128, 2) void gemm_out_kernel(
    const __half* __restrict__ A, const __half* __restrict__ Bw,
    const float* __restrict__ bias, float* __restrict__ C)
{
    int bn = blockIdx.x, bm = blockIdx.y;
    gemm_core_h(A + (size_t)bm * 128 * DM, Bw + bn * 128, DM, bias + bn * 128,
        [&](wmma::fragment<wmma::accumulator, 16, 16, 16, float> (&acc)[4][4],
            int wm, int wn) {
            float* Cp = C + (size_t)(bm * 128 + wm * 64) * DM + bn * 128 + wn * 64;
#pragma unroll
            for (int i = 0; i < 4; i++)
#pragma unroll
                for (int j = 0; j < 4; j++)
                    wmma::store_matrix_sync(Cp + (size_t)(i * 16) * DM + j * 16,
                                            acc[i][j], DM, wmma::mem_row_major);
        });
}

// ---------------------------------------------------------------------------
// ropeKV: K rope -> KpH (fp16, [b][t][grp][d]); V -> VpH (fp16 transposed
// [b][grp][d][t]). Q rope is fused into the attention kernel.
// ---------------------------------------------------------------------------
#define ROPE_NK (MTOT * NG * 32)
#define VPERM_N (MTOT * KVD)

__global__ void ropeKV_kernel(const float* __restrict__ Kd, __half* __restrict__ Kp,
                              const float* __restrict__ Vd, __half* __restrict__ Vp)
{
    int idx = blockIdx.x * blockDim.x + threadIdx.x;
    if (idx < ROPE_NK) {
        int i = idx & 31;
        int rest = idx >> 5;
        int t = (rest / NG) % TT;
        float freq = expf(-((2.0f * (float)i) / (float)DH) * 9.210340371976184f);
        float ang = (float)t * freq;
        float s, c;
        sincosf(ang, &s, &c);
        const float* p = Kd + (size_t)rest * DH + 2 * i;
        float xe = p[0], xo = p[1];
        Kp[(size_t)rest * DH + 2 * i]     = __float2half(xe * c - xo * s);
        Kp[(size_t)rest * DH + 2 * i + 1] = __float2half(xe * s + xo * c);
        return;
    }
    idx -= ROPE_NK;
    if (idx >= VPERM_N) return;
    int t = idx & (TT - 1);
    int rest2 = idx >> 11;
    int d = rest2 & (DH - 1);
    int bg = rest2 >> 6;
    int b = bg >> 2, grp = bg & 3;
    float v = Vd[((size_t)(b * TT + t)) * KVD + grp * DH + d];
    Vp[idx] = __float2half(v);
}

// ---------------------------------------------------------------------------
// FP16 attention: Q-rope fused into fragment load; ex2.f16x2 softmax; ones-
// column row sums; fully-masked jp blocks skipped.
// ---------------------------------------------------------------------------
#define RQ   128
#define TK   64
#define KLDH 72
#define VROWS 72
#define ATT_SMEM ((2 * TK * KLDH + 2 * VROWS * KLDH) * 2)   // 38016 B

__global__ __launch_bounds__(128, 2) void attn_f16_kernel(
    const float* __restrict__ Q, const __half* __restrict__ K,
    const __half* __restrict__ V, __half* __restrict__ O)
{
    extern __shared__ __half smh[];
    __half* Kb = smh;                    // 2 x 64 x 72
    __half* Vb = smh + 2 * TK * KLDH;    // 2 x 72 x 72

    int tid = threadIdx.x, warp = tid >> 5, lane = tid & 31;
    int g = lane >> 2, tau = lane & 3;

    int idx = blockIdx.x;
    int qblk = 15 - (idx >> 5);          // heavy blocks first
    int bh = idx & 31;
    int h = bh & 15, b = bh >> 4;
    int grp = h / HPG;
    int q0 = qblk * RQ;
    int ntiles = 2 * (qblk + 1);
    const float scale = 0.125f * 1.4426950408889634f;   // 1/sqrt(dh) * log2(e)

    const __half* KbaseH = K + (size_t)b * TT * KVD + grp * DH;
    const __half* VbaseH = V + (size_t)(b * NG + grp) * DH * TT;

    auto issue = [&](int kt) {
        int buf = kt & 1, kb = kt * TK;
        __half* kd = &Kb[buf * TK * KLDH];
        __half* vd = &Vb[buf * VROWS * KLDH];
        for (int i = tid; i < 512; i += 128) {
            int r = i >> 3, c = (i & 7) << 3;
            cp16(&kd[r * KLDH + c], KbaseH + (size_t)(kb + r) * KVD + c);
            cp16(&vd[r * KLDH + c], VbaseH + (size_t)r * TT + kb + c);
        }
        cp_commit();
    };
    issue(0);
    issue(1);

    // ones-row 64 for both V buffers (rows 65..71 unused garbage; their mma
    // outputs are never read)
    for (int i = tid; i < 2 * KLDH; i += 128) {
        int buf = i / KLDH, c = i % KLDH;
        Vb[buf * VROWS * KLDH + 64 * KLDH + c] = __float2half(1.0f);
    }

    // Q a-frags with fused RoPE (adjacent even/odd dh pairs per register)
    unsigned int qa[2][4][4];
#pragma unroll
    for (int m = 0; m < 2; m++) {
        int row0 = q0 + warp * 32 + m * 16 + g;      // t for v0/v2
        int row1 = row0 + 8;                         // t for v1/v3
        const float* qp = Q + ((size_t)(b * TT + row0 - g)) * DM + h * DH;
#pragma unroll
        for (int c = 0; c < 4; c++) {
            int i0 = c * 8 + tau;                    // pair index for cols c*16+2tau
            int i1 = i0 + 4;                         // pair index for cols c*16+8+2tau
            float2 v0 = *(const float2*)(qp + (size_t)g * DM + c * 16 + 2 * tau);
            float2 v1 = *(const float2*)(qp + (size_t)(g + 8) * DM + c * 16 + 2 * tau);
            float2 v2 = *(const float2*)(qp + (size_t)g * DM + c * 16 + 8 + 2 * tau);
            float2 v3 = *(const float2*)(qp + (size_t)(g + 8) * DM + c * 16 + 8 + 2 * tau);
            float2 r0 = rope_pair(v0.x, v0.y, row0 & (TT - 1), i0, scale);
            float2 r1 = rope_pair(v1.x, v1.y, row1 & (TT - 1), i0, scale);
            float2 r2 = rope_pair(v2.x, v2.y, row0 & (TT - 1), i1, scale);
            float2 r3 = rope_pair(v3.x, v3.y, row1 & (TT - 1), i1, scale);
            qa[m][c][0] = pack_h2(r0.x, r0.y);
            qa[m][c][1] = pack_h2(r1.x, r1.y);
            qa[m][c][2] = pack_h2(r2.x, r2.y);
            qa[m][c][3] = pack_h2(r3.x, r3.y);
        }
    }

    // oc[m][0..7] = output dh blocks; oc[m][8] = row sums (ones column)
    float oc[2][9][4];
#pragma unroll
    for (int m = 0; m < 2; m++)
#pragma unroll
        for (int n = 0; n < 9; n++)
            oc[m][n][0] = oc[m][n][1] = oc[m][n][2] = oc[m][n][3] = 0.0f;

    int rowmax = q0 + warp * 32 + 31;    // warp's last q row

    for (int kt = 0; kt < ntiles; kt++) {
        if (kt + 1 < ntiles) cp_wait<1>(); else cp_wait<0>();
        __syncthreads();
        const __half* Kt = &Kb[(kt & 1) * TK * KLDH];
        const __half* Vt = &Vb[(kt & 1) * VROWS * KLDH];
        bool need_mask = (kt >= 2 * qblk);
        int kcol = kt * TK;

#pragma unroll
        for (int jp = 0; jp < 4; jp++) {
            // skip jp blocks fully above the causal diagonal (warp-uniform)
            if (need_mask && (kcol + jp * 16 > rowmax)) continue;

            float sa[2][2][4];
#pragma unroll
            for (int jj = 0; jj < 2; jj++)
#pragma unroll
                for (int m = 0; m < 2; m++)
                    sa[jj][m][0] = sa[jj][m][1] = sa[jj][m][2] = sa[jj][m][3] = 0.0f;
#pragma unroll
            for (int c = 0; c < 4; c++) {
#pragma unroll
                for (int jj = 0; jj < 2; jj++) {
                    const __half* krow = &Kt[((jp * 2 + jj) * 8 + g) * KLDH];
                    unsigned int b0 = *(const unsigned int*)(krow + c * 16 + 2 * tau);
                    unsigned int b1 = *(const unsigned int*)(krow + c * 16 + 8 + 2 * tau);
#pragma unroll
                    for (int m = 0; m < 2; m++)
                        mma_f16(sa[jj][m][0], sa[jj][m][1], sa[jj][m][2], sa[jj][m][3],
                                qa[m][c][0], qa[m][c][1], qa[m][c][2], qa[m][c][3],
                                b0, b1);
                }
            }

            // mask + pack + ex2.f16x2 (p = 2^(log2e*s) = e^s)
            unsigned int af[2][4];
#pragma unroll
            for (int m = 0; m < 2; m++) {
#pragma unroll
                for (int jj = 0; jj < 2; jj++) {
                    float s0 = sa[jj][m][0], s1 = sa[jj][m][1];
                    float s2 = sa[jj][m][2], s3 = sa[jj][m][3];
                    if (need_mask) {
                        int j = jp * 2 + jj;
                        int c = kcol + j * 8 + 2 * tau;
                        int row0 = q0 + warp * 32 + m * 16 + g;
                        int row1 = row0 + 8;
                        if (c     > row0) s0 = -INFINITY;
                        if (c + 1 > row0) s1 = -INFINITY;
                        if (c     > row1) s2 = -INFINITY;
                        if (c + 1 > row1) s3 = -INFINITY;
                    }
                    af[m][jj * 2 + 0] = ex2_h2(pack_h2(s0, s1));
                    af[m][jj * 2 + 1] = ex2_h2(pack_h2(s2, s3));
                }
            }

            // O += P @ [V ; ones]: n=0..7 output, n=8 row sums
#pragma unroll
            for (int n = 0; n < 9; n++) {
                const __half* vrow = &Vt[(n * 8 + g) * KLDH];
                unsigned int b0 = *(const unsigned int*)(vrow + jp * 16 + 2 * tau);
                unsigned int b1 = *(const unsigned int*)(vrow + jp * 16 + 8 + 2 * tau);
#pragma unroll
                for (int m = 0; m < 2; m++)
                    mma_f16(oc[m][n][0], oc[m][n][1], oc[m][n][2], oc[m][n][3],
                            af[m][0], af[m][1], af[m][2], af[m][3], b0, b1);
            }
        }
        __syncthreads();
        if (kt + 2 < ntiles) issue(kt + 2);
    }

    // row sums in oc[m][8] col0 (lanes tau==0); broadcast in quad
#pragma unroll
    for (int m = 0; m < 2; m++) {
        float rs0 = __shfl_sync(0xffffffffu, oc[m][8][0], lane & ~3);
        float rs1 = __shfl_sync(0xffffffffu, oc[m][8][2], lane & ~3);
        float inv0 = 1.0f / rs0, inv1 = 1.0f / rs1;
        int row0 = q0 + warp * 32 + m * 16 + g;
        __half* o0 = O + ((size_t)(b * TT + row0)) * DM + h * DH + 2 * tau;
        __half* o1 = O + ((size_t)(b * TT + row0 + 8)) * DM + h * DH + 2 * tau;
#pragma unroll
        for (int n = 0; n < 8; n++) {
            *(unsigned int*)(o0 + n * 8) = pack_h2(oc[m][n][0] * inv0, oc[m][n][1] * inv0);
            *(unsigned int*)(o1 + n * 8) = pack_h2(oc[m][n][2] * inv1, oc[m][n][3] * inv1);
        }
    }
}

// ---------------------------------------------------------------------------
extern "C" void kernel_launch(void* const* d_in, const int* in_sizes, int n_in,
                              void* d_out, int out_size)
{
    const float* x  = (const float*)d_in[0];
    const float* Wq = (const float*)d_in[1];
    const float* bq = (const float*)d_in[2];
    const float* Wk = (const float*)d_in[3];
    const float* bk = (const float*)d_in[4];
    const float* Wv = (const float*)d_in[5];
    const float* bv = (const float*)d_in[6];
    const float* Wo = (const float*)d_in[7];
    const float* bo = (const float*)d_in[8];
    float* out = (float*)d_out;

    float *Q, *Kp, *Vp, *bqkv;
    __half *KpH, *VpH, *Ah, *Xh, *wqkvh, *woh;
    cudaGetSymbolAddress((void**)&Q,     g_Q);
    cudaGetSymbolAddress((void**)&Kp,    g_K);
    cudaGetSymbolAddress((void**)&Vp,    g_V);
    cudaGetSymbolAddress((void**)&KpH,   g_KpH);
    cudaGetSymbolAddress((void**)&VpH,   g_VpH);
    cudaGetSymbolAddress((void**)&Ah,    g_Ah);
    cudaGetSymbolAddress((void**)&Xh,    g_Xh);
    cudaGetSymbolAddress((void**)&wqkvh, g_Wqkvh);
    cudaGetSymbolAddress((void**)&bqkv,  g_bqkv);
    cudaGetSymbolAddress((void**)&woh,   g_Woh);

    cudaFuncSetAttribute((const void*)gemm_qkv_kernel,
                         cudaFuncAttributeMaxDynamicSharedMemorySize, GSMEMH);
    cudaFuncSetAttribute((const void*)gemm_out_kernel,
                         cudaFuncAttributeMaxDynamicSharedMemorySize, GSMEMH);
    cudaFuncSetAttribute((const void*)attn_f16_kernel,
                         cudaFuncAttributeMaxDynamicSharedMemorySize, ATT_SMEM);

    // prepass: convert + pack (fp16 GEMM operands)
    prep_kernel<<<(N4_TOT + 255) / 256, 256>>>(x, Wq, Wk, Wv, Wo, bq, bk, bv,
                                               Xh, wqkvh, woh, bqkv);

    // fused QKV projection
    dim3 gqkv(NQKV / 128, MTOT / 128);    // (12, 32)
    gemm_qkv_kernel<<<gqkv, 128, GSMEMH>>>(Xh, wqkvh, bqkv, Q, Kp, Vp);

    // K rope -> fp16; V transpose -> fp16 (Q rope fused in attention)
    int nr = ROPE_NK + VPERM_N;
    ropeKV_kernel<<<(nr + 255) / 256, 256>>>(Kp, KpH, Vp, VpH);

    // fp16 attention (reads raw Q, applies rope in-register) -> fp16 output
    attn_f16_kernel<<<512, 128, ATT_SMEM>>>(Q, KpH, VpH, Ah);

    // output projection
    dim3 go(DM / 128, MTOT / 128);        // (8, 32)
    gemm_out_kernel<<<go, 128, GSMEMH>>>(Ah, woh, bo, out);
}